// round 13
// baseline (speedup 1.0000x reference)
#include <cuda_runtime.h>
#include <cuda_bf16.h>
#include <cuda_fp16.h>
#include <mma.h>
#include <math.h>
#include <stdint.h>

using namespace nvcuda;

#define S_   1024
#define DM_  1024
#define B_   8
#define H_   16
#define D_   64

// ---------------- scratch (__device__ globals; no allocation) ----------------
__device__ __half g_Qh[B_*H_*S_*D_];   // projected Q [b,h,s,d] fp16
__device__ __half g_Kh[B_*H_*S_*D_];   // projected K
__device__ __half g_Vh[B_*H_*S_*D_];   // projected V
__device__ __half g_Ac0[B_*S_*DM_];    // converted Q input; then X fp16 hi
__device__ __half g_Ac1[B_*S_*DM_];    // converted K input; then X fp16 residual
__device__ __half g_Ac2[B_*S_*DM_];    // converted V input
__device__ __half g_W4[4*DM_*DM_];     // transposed fp16 weights [n][k]: Wq,Wk,Wv,Wo

// ---------------- helpers ----------------
__device__ __forceinline__ uint32_t smem_u32(const void* p) {
    uint32_t a;
    asm("{ .reg .u64 t; cvta.to.shared.u64 t, %1; cvt.u32.u64 %0, t; }"
        : "=r"(a) : "l"(p));
    return a;
}
__device__ __forceinline__ void cp16(uint32_t dst, const void* src) {
    asm volatile("cp.async.cg.shared.global [%0], [%1], 16;" :: "r"(dst), "l"(src));
}
__device__ __forceinline__ uint32_t pack2h(float a, float b) {
    __half ha = __float2half_rn(a), hb = __float2half_rn(b);
    return (uint32_t)__half_as_ushort(ha) |
           ((uint32_t)__half_as_ushort(hb) << 16);
}
__device__ __forceinline__ uint32_t pack2hres(float a, float b, float* ra, float* rb) {
    __half ha = __float2half_rn(a), hb = __float2half_rn(b);
    *ra = a - __half2float(ha);
    *rb = b - __half2float(hb);
    return (uint32_t)__half_as_ushort(ha) |
           ((uint32_t)__half_as_ushort(hb) << 16);
}

// ---------------- conversion kernels ----------------
__global__ __launch_bounds__(256) void cvt_act_h3(
    const float4* __restrict__ Q, const float4* __restrict__ K,
    const float4* __restrict__ V, int n4)
{
    int i = blockIdx.x * 256 + threadIdx.x;
    if (i >= n4) return;
    int z = blockIdx.y;
    const float4* src = (z == 0) ? Q : (z == 1) ? K : V;
    uint2* dst = (uint2*)((z == 0) ? g_Ac0 : (z == 1) ? g_Ac1 : g_Ac2);
    float4 v = src[i];
    uint2 h;
    h.x = pack2h(v.x, v.y);
    h.y = pack2h(v.z, v.w);
    dst[i] = h;
}

// weight transpose fp16, 4-way batch: z<3 src=W[h][k][d] (n=h*64+d); z=3 src=Wo[k][n]
__global__ __launch_bounds__(256) void split_wT_h4(
    const float* __restrict__ Wq, const float* __restrict__ Wk,
    const float* __restrict__ Wv, const float* __restrict__ Wo)
{
    __shared__ float t[32][33];
    int k0 = blockIdx.x * 32, n0 = blockIdx.y * 32;
    int z = blockIdx.z;
    const float* W = (z == 0) ? Wq : (z == 1) ? Wk : (z == 2) ? Wv : Wo;
    __half* out = g_W4 + (size_t)z * DM_ * DM_;
    int tx = threadIdx.x, ty = threadIdx.y;
    #pragma unroll
    for (int i = 0; i < 4; i++) {
        int k = k0 + ty + 8*i, n = n0 + tx;
        float v = (z < 3) ? W[(((size_t)(n >> 6)) * 1024 + k) * 64 + (n & 63)]
                          : W[(size_t)k * 1024 + n];
        t[ty + 8*i][tx] = v;
    }
    __syncthreads();
    #pragma unroll
    for (int i = 0; i < 4; i++) {
        int n = n0 + ty + 8*i, k = k0 + tx;
        out[(size_t)n * 1024 + k] = __float2half_rn(t[tx][ty + 8*i]);
    }
}

// ---------------- fragment typedefs / sizes ----------------
#define LDSM   40
#define EPLD   132
// proj GEMM (M=256,N=128, 2 mats, 3 stages)
#define SSTR1  (256*LDSM*2 + 128*LDSM*2)          // 30720 per stage (A then B)
#define SOFF_B1 (256*LDSM*2)                       // 20480
#define GSMEM1 (3*SSTR1 + 16*128*4)                // 100352 (epi 67584 fits)
// out GEMM (M=256,N=128, 3 mats, 2 stages)
#define SSTR2  (2*256*LDSM*2 + 128*LDSM*2)        // 51200
#define SOFF_AL2 (256*LDSM*2)                      // 20480
#define SOFF_B2  (2*256*LDSM*2)                    // 40960
#define GSMEM2 (2*SSTR2 + 16*128*4)                // 110592

typedef wmma::fragment<wmma::matrix_a, 16,16,16, __half, wmma::row_major> HFragA;
typedef wmma::fragment<wmma::matrix_b, 16,16,16, __half, wmma::col_major> HFragB;
typedef wmma::fragment<wmma::matrix_b, 16,16,16, __half, wmma::row_major> HFragBr;
typedef wmma::fragment<wmma::accumulator, 16,16,16, float> FragC;

// ---------------- fp16 single-pass GEMM (QKV proj, M=256 tile, 3-stage) -----
__device__ __forceinline__ void issue_stage_p(
    const __half* __restrict__ Ah, const __half* __restrict__ Bh,
    uint32_t sbase, int stage, int m0, int n0, int k0, int tid)
{
    #pragma unroll
    for (int u = 0; u < 6; u++) {
        int c = u * 256 + tid;             // 1536 chunks of 16B
        uint32_t dst;
        const __half* g;
        if (c < 1024) {                    // A: 256 rows x 4 chunks
            int r = c >> 2, cc = c & 3;
            g = Ah + (size_t)(m0 + r) * 1024 + k0 + cc * 8;
            dst = sbase + (uint32_t)(stage * SSTR1 + r * 80 + cc * 16);
        } else {                           // B: 128 rows x 4 chunks
            int cb = c - 1024;
            int r = cb >> 2, cc = cb & 3;
            g = Bh + (size_t)(n0 + r) * 1024 + k0 + cc * 8;
            dst = sbase + (uint32_t)(stage * SSTR1 + SOFF_B1 + r * 80 + cc * 16);
        }
        cp16(dst, g);
    }
    asm volatile("cp.async.commit_group;" ::: "memory");
}

__global__ __launch_bounds__(256, 1) void mma_gemm_h1b(
    const float* __restrict__ bq, const float* __restrict__ bk,
    const float* __restrict__ bv)
{
    extern __shared__ char sm[];
    float* sBias = (float*)(sm + 3 * SSTR1);
    const uint32_t sbase = smem_u32(sm);
    const int tid = threadIdx.x;
    const int wid = tid >> 5;
    const int wm = wid >> 1;     // 0..3 (64-row slices of 256)
    const int wn = wid & 1;      // 0..1 (64-col slices of 128)
    const int m0 = blockIdx.y * 256;
    const int n0 = blockIdx.x * 128;
    const int z  = blockIdx.z;

    const __half* Ah = (z == 0) ? g_Ac0 : (z == 1) ? g_Ac1 : g_Ac2;
    const __half* Bh = g_W4 + (size_t)z * DM_ * DM_;
    const float* bias = (z == 0) ? bq : (z == 1) ? bk : bv;
    __half* outH = (z == 0) ? g_Qh : (z == 1) ? g_Kh : g_Vh;

    for (int idx = tid; idx < 16 * 128; idx += 256)
        sBias[idx] = bias[n0 + (idx & 127)];

    issue_stage_p(Ah, Bh, sbase, 0, m0, n0, 0, tid);
    issue_stage_p(Ah, Bh, sbase, 1, m0, n0, 32, tid);
    __syncthreads();

    FragC acc[4][4];
    #pragma unroll
    for (int i = 0; i < 4; i++)
        #pragma unroll
        for (int j = 0; j < 4; j++)
            wmma::load_matrix_sync(acc[i][j], sBias + wn*64 + j*16, 128, wmma::mem_row_major);

    for (int kc = 0; kc < 32; kc++) {
        const int s = kc % 3;
        if (kc + 2 < 32) {
            issue_stage_p(Ah, Bh, sbase, (kc + 2) % 3, m0, n0, (kc + 2) * 32, tid);
            asm volatile("cp.async.wait_group 2;" ::: "memory");
        } else if (kc + 1 < 32) {
            asm volatile("cp.async.wait_group 1;" ::: "memory");
        } else {
            asm volatile("cp.async.wait_group 0;" ::: "memory");
        }
        __syncthreads();

        const __half* stg = (const __half*)(sm + s * SSTR1);
        const __half* sAh = stg;
        const __half* sBh = stg + 256 * LDSM;

        #pragma unroll
        for (int ks = 0; ks < 2; ks++) {
            HFragA ah[4];
            HFragB bh[4];
            #pragma unroll
            for (int i = 0; i < 4; i++)
                wmma::load_matrix_sync(ah[i], sAh + (wm*64 + i*16) * LDSM + ks*16, LDSM);
            #pragma unroll
            for (int j = 0; j < 4; j++)
                wmma::load_matrix_sync(bh[j], sBh + (wn*64 + j*16) * LDSM + ks*16, LDSM);
            #pragma unroll
            for (int i = 0; i < 4; i++)
                #pragma unroll
                for (int j = 0; j < 4; j++)
                    wmma::mma_sync(acc[i][j], ah[i], bh[j], acc[i][j]);
        }
        __syncthreads();
    }

    // epilogue: two 128-row half passes through smem
    float* sEpi = (float*)sm;
    #pragma unroll
    for (int p = 0; p < 2; p++) {
        __syncthreads();
        if ((wm >> 1) == p) {
            const int wm2 = wm & 1;
            #pragma unroll
            for (int i = 0; i < 4; i++)
                #pragma unroll
                for (int j = 0; j < 4; j++)
                    wmma::store_matrix_sync(sEpi + (wm2*64 + i*16) * EPLD + wn*64 + j*16,
                                            acc[i][j], EPLD, wmma::mem_row_major);
        }
        __syncthreads();
        #pragma unroll
        for (int u = 0; u < 32; u++) {
            int e2 = u * 256 + tid;         // 8192 pairs
            int r = e2 >> 6;
            int c = (e2 & 63) * 2;
            float v0 = sEpi[r * EPLD + c];
            float v1 = sEpi[r * EPLD + c + 1];
            uint32_t hv = pack2h(v0, v1);
            const int m = m0 + p * 128 + r, n = n0 + c;
            const int b = m >> 10, srow = m & 1023;
            const int h = n >> 6,  d = n & 63;
            size_t addr = ((((size_t)(b*16 + h)) * 1024 + srow) * 64 + d);
            *(uint32_t*)(outH + addr) = hv;
        }
    }
}

// ---------------- fp16x2 GEMM (output projection, M=256 tile, fp32 out) -----
__device__ __forceinline__ void issue_stage_o(
    uint32_t sbase, int stage, int m0, int n0, int k0, int tid)
{
    #pragma unroll
    for (int u = 0; u < 10; u++) {
        int c = u * 256 + tid;             // 2560 chunks of 16B
        uint32_t dst;
        const __half* g;
        if (c < 1024) {                    // A hi
            int r = c >> 2, cc = c & 3;
            g = g_Ac0 + (size_t)(m0 + r) * 1024 + k0 + cc * 8;
            dst = sbase + (uint32_t)(stage * SSTR2 + r * 80 + cc * 16);
        } else if (c < 2048) {             // A residual
            int cb = c - 1024;
            int r = cb >> 2, cc = cb & 3;
            g = g_Ac1 + (size_t)(m0 + r) * 1024 + k0 + cc * 8;
            dst = sbase + (uint32_t)(stage * SSTR2 + SOFF_AL2 + r * 80 + cc * 16);
        } else {                           // B (Wo)
            int cb = c - 2048;
            int r = cb >> 2, cc = cb & 3;
            g = g_W4 + (size_t)3 * DM_ * DM_ + (size_t)(n0 + r) * 1024 + k0 + cc * 8;
            dst = sbase + (uint32_t)(stage * SSTR2 + SOFF_B2 + r * 80 + cc * 16);
        }
        cp16(dst, g);
    }
    asm volatile("cp.async.commit_group;" ::: "memory");
}

__global__ __launch_bounds__(256, 1) void mma_gemm_h2f(
    const float* __restrict__ bias, float* __restrict__ outF)
{
    extern __shared__ char sm[];
    float* sBias = (float*)(sm + 2 * SSTR2);
    const uint32_t sbase = smem_u32(sm);
    const int tid = threadIdx.x;
    const int wid = tid >> 5;
    const int wm = wid >> 1;
    const int wn = wid & 1;
    const int m0 = blockIdx.y * 256;
    const int n0 = blockIdx.x * 128;

    for (int idx = tid; idx < 16 * 128; idx += 256)
        sBias[idx] = bias[n0 + (idx & 127)];

    issue_stage_o(sbase, 0, m0, n0, 0, tid);
    __syncthreads();

    FragC acc[4][4];
    #pragma unroll
    for (int i = 0; i < 4; i++)
        #pragma unroll
        for (int j = 0; j < 4; j++)
            wmma::load_matrix_sync(acc[i][j], sBias + wn*64 + j*16, 128, wmma::mem_row_major);

    for (int kc = 0; kc < 32; kc++) {
        const int s = kc & 1;
        if (kc + 1 < 32) {
            issue_stage_o(sbase, s ^ 1, m0, n0, (kc + 1) * 32, tid);
            asm volatile("cp.async.wait_group 1;" ::: "memory");
        } else {
            asm volatile("cp.async.wait_group 0;" ::: "memory");
        }
        __syncthreads();

        const __half* stg = (const __half*)(sm + s * SSTR2);
        const __half* sAh = stg;
        const __half* sAl = stg + 256 * LDSM;
        const __half* sBh = stg + 2 * 256 * LDSM;

        #pragma unroll
        for (int ks = 0; ks < 2; ks++) {
            HFragA ah[4], al[4];
            HFragB bh[4];
            #pragma unroll
            for (int i = 0; i < 4; i++) {
                wmma::load_matrix_sync(ah[i], sAh + (wm*64 + i*16) * LDSM + ks*16, LDSM);
                wmma::load_matrix_sync(al[i], sAl + (wm*64 + i*16) * LDSM + ks*16, LDSM);
            }
            #pragma unroll
            for (int j = 0; j < 4; j++)
                wmma::load_matrix_sync(bh[j], sBh + (wn*64 + j*16) * LDSM + ks*16, LDSM);
            #pragma unroll
            for (int i = 0; i < 4; i++)
                #pragma unroll
                for (int j = 0; j < 4; j++) {
                    wmma::mma_sync(acc[i][j], ah[i], bh[j], acc[i][j]);
                    wmma::mma_sync(acc[i][j], al[i], bh[j], acc[i][j]);
                }
        }
        __syncthreads();
    }

    #pragma unroll
    for (int i = 0; i < 4; i++) {
        const int m = m0 + wm*64 + i*16;
        #pragma unroll
        for (int j = 0; j < 4; j++) {
            const int n = n0 + wn*64 + j*16;
            wmma::store_matrix_sync(outF + (size_t)m * 1024 + n, acc[i][j],
                                    1024, wmma::mem_row_major);
        }
    }
}

// ---------------- tensor-core flash attention v5 (fp16, unchanged) ----------
#define ALD 72
#define SLD 68
#define TQB 9216
#define oQ   0
#define oKV  18432
#define oP   55296
#define oS   73728
#define ATTN_SMEM 108544
#define KVSTG (2 * TQB)

__global__ __launch_bounds__(256, 2) void attn_mma(const int* __restrict__ pad)
{
    extern __shared__ char sm[];
    const uint32_t sbase = smem_u32(sm);
    const int tid  = threadIdx.x;
    const int w    = tid >> 5, lane = tid & 31;
    const int g    = w >> 2,   wr   = w & 3;
    const int bx   = blockIdx.x;
    const int bh   = blockIdx.y;
    const int b    = bh >> 4, h = bh & 15;
    const int padb = pad[b];
    const int tlim = S_ - padb;
    const int qt   = bx * 2 + g;
    const int q0   = qt * 64;
    const size_t hoff = (size_t)bh * S_ * D_;

    float* sSg = (float*)(sm + oS + g * 17408);
    __half* sPg = (__half*)(sm + oP + g * TQB);
    const __half* sQ = (const __half*)(sm + oQ + g * TQB);

    #pragma unroll
    for (int u = 0; u < 4; u++) {
        int c = u * 256 + tid;
        int gm = c >> 9;
        int rc = c & 511;
        int r = rc >> 3, cc = rc & 7;
        const __half* src = g_Qh + hoff + (size_t)((bx*2 + gm) * 64 + r) * 64 + cc * 8;
        cp16(sbase + oQ + (uint32_t)(gm * TQB + r * 144 + cc * 16), src);
    }
    #pragma unroll
    for (int u = 0; u < 4; u++) {
        int c = u * 256 + tid;
        int mat = c >> 9;
        int rc = c & 511;
        int r = rc >> 3, cc = rc & 7;
        const __half* src = (mat == 0 ? g_Kh : g_Vh) + hoff + (size_t)r * 64 + cc * 8;
        cp16(sbase + oKV + (uint32_t)(mat * TQB + r * 144 + cc * 16), src);
    }
    asm volatile("cp.async.commit_group;" ::: "memory");

    const int jtLast = (padb == 0) ? 15 : min(bx * 2 + 1, (tlim - 1) >> 6);

    const int lr = lane >> 1, half = lane & 1;
    const int srow = q0 + wr * 16 + lr;

    float o[32];
    #pragma unroll
    for (int c = 0; c < 32; c++) o[c] = 0.f;
    float mrow = -INFINITY, lrow = 0.f;

    for (int jt = 0; jt <= jtLast; jt++) {
        const int s = jt & 1;
        const int t0 = jt * 64;
        if (jt < jtLast) {
            const int tn = (jt + 1) * 64;
            #pragma unroll
            for (int u = 0; u < 4; u++) {
                int c = u * 256 + tid;
                int mat = c >> 9;
                int rc = c & 511;
                int r = rc >> 3, cc = rc & 7;
                const __half* src = (mat == 0 ? g_Kh : g_Vh) + hoff + (size_t)(tn + r) * 64 + cc * 8;
                cp16(sbase + oKV + (uint32_t)((s ^ 1) * KVSTG + mat * TQB + r * 144 + cc * 16), src);
            }
            asm volatile("cp.async.commit_group;" ::: "memory");
            asm volatile("cp.async.wait_group 1;" ::: "memory");
        } else {
            asm volatile("cp.async.wait_group 0;" ::: "memory");
        }
        __syncthreads();

        const bool act = (padb == 0) || (jt <= qt && t0 < tlim);
        if (act) {
            const __half* sK = (const __half*)(sm + oKV + s * KVSTG);
            const __half* sV = (const __half*)(sm + oKV + s * KVSTG + TQB);

            {
                HFragA qf[4];
                #pragma unroll
                for (int ks = 0; ks < 4; ks++)
                    wmma::load_matrix_sync(qf[ks], sQ + (wr*16) * ALD + ks*16, ALD);
                FragC acc[4];
                #pragma unroll
                for (int j = 0; j < 4; j++) wmma::fill_fragment(acc[j], 0.f);
                #pragma unroll
                for (int j = 0; j < 4; j++) {
                    #pragma unroll
                    for (int ks = 0; ks < 4; ks++) {
                        HFragB kf;
                        wmma::load_matrix_sync(kf, sK + (j*16) * ALD + ks*16, ALD);
                        wmma::mma_sync(acc[j], qf[ks], kf, acc[j]);
                    }
                }
                #pragma unroll
                for (int j = 0; j < 4; j++)
                    wmma::store_matrix_sync(sSg + (wr*16) * SLD + j*16, acc[j],
                                            SLD, wmma::mem_row_major);
            }
            __syncwarp();

            float alpha;
            {
                const float4* Srow4 = (const float4*)(sSg + (wr*16 + lr) * SLD + half * 32);
                const int tbase = t0 + half * 32;
                float v[32];
                #pragma unroll
                for (int q4 = 0; q4 < 8; q4++) {
                    float4 f = Srow4[q4];
                    v[q4*4+0] = f.x; v[q4*4+1] = f.y; v[q4*4+2] = f.z; v[q4*4+3] = f.w;
                }
                float mloc = -INFINITY;
                #pragma unroll
                for (int c = 0; c < 32; c++) {
                    const int t = tbase + c;
                    float val = v[c] * 0.03125f;
                    if ((t > srow) | (t >= tlim) | (padb == 0)) val -= 1e9f;
                    v[c] = val;
                    mloc = fmaxf(mloc, val);
                }
                mloc = fmaxf(mloc, __shfl_xor_sync(0xffffffffu, mloc, 1));
                const float mnew = fmaxf(mrow, mloc);
                alpha = __expf(mrow - mnew);
                uint32_t* Pr32 = (uint32_t*)(sPg + (wr*16 + lr) * ALD + half * 32);
                float lsum = 0.f;
                #pragma unroll
                for (int c = 0; c < 32; c += 2) {
                    float p0 = __expf(v[c]   - mnew);
                    float p1 = __expf(v[c+1] - mnew);
                    lsum += p0; lsum += p1;
                    Pr32[c >> 1] = pack2h(p0, p1);
                }
                lsum += __shfl_xor_sync(0xffffffffu, lsum, 1);
                lrow = lrow * alpha + lsum;
                mrow = mnew;
            }
            __syncwarp();

            {
                HFragA pf[4];
                #pragma unroll
                for (int ks = 0; ks < 4; ks++)
                    wmma::load_matrix_sync(pf[ks], sPg + (wr*16) * ALD + ks*16, ALD);
                FragC oa[4];
                #pragma unroll
                for (int n = 0; n < 4; n++) wmma::fill_fragment(oa[n], 0.f);
                #pragma unroll
                for (int n = 0; n < 4; n++) {
                    #pragma unroll
                    for (int ks = 0; ks < 4; ks++) {
                        HFragBr vf;
                        wmma::load_matrix_sync(vf, sV + (ks*16) * ALD + n*16, ALD);
                        wmma::mma_sync(oa[n], pf[ks], vf, oa[n]);
                    }
                }
                #pragma unroll
                for (int n = 0; n < 4; n++)
                    wmma::store_matrix_sync(sSg + (wr*16) * SLD + n*16, oa[n],
                                            SLD, wmma::mem_row_major);
            }
            __syncwarp();

            {
                const float4* Pv4 = (const float4*)(sSg + (wr*16 + lr) * SLD + half * 32);
                #pragma unroll
                for (int q4 = 0; q4 < 8; q4++) {
                    float4 f = Pv4[q4];
                    o[q4*4+0] = o[q4*4+0] * alpha + f.x;
                    o[q4*4+1] = o[q4*4+1] * alpha + f.y;
                    o[q4*4+2] = o[q4*4+2] * alpha + f.z;
                    o[q4*4+3] = o[q4*4+3] * alpha + f.w;
                }
            }
        }
        __syncthreads();
    }

    {
        const float inv = 1.f / lrow;
        const size_t base = ((size_t)(b * S_ + srow)) * DM_ + h * 64 + half * 32;
        #pragma unroll
        for (int c = 0; c < 32; c += 2) {
            float v0 = o[c] * inv, v1 = o[c+1] * inv;
            float r0, r1;
            uint32_t hv = pack2hres(v0, v1, &r0, &r1);
            uint32_t lv = pack2h(r0, r1);
            *(uint32_t*)(g_Ac0 + base + c) = hv;
            *(uint32_t*)(g_Ac1 + base + c) = lv;
        }
    }
}

// ---------------------------------------------------------------------------
extern "C" void kernel_launch(void* const* d_in, const int* in_sizes, int n_in,
                              void* d_out, int out_size)
{
    const float* Q   = (const float*)d_in[0];
    const float* K   = (const float*)d_in[1];
    const float* V   = (const float*)d_in[2];
    const int*   pad = (const int*)  d_in[3];
    const float* Wq  = (const float*)d_in[4];
    const float* bq  = (const float*)d_in[5];
    const float* Wk  = (const float*)d_in[6];
    const float* bk  = (const float*)d_in[7];
    const float* Wv  = (const float*)d_in[8];
    const float* bv  = (const float*)d_in[9];
    const float* Wo  = (const float*)d_in[10];
    const float* bo  = (const float*)d_in[11];
    float* out = (float*)d_out;

    cudaFuncSetAttribute(mma_gemm_h1b,
                         cudaFuncAttributeMaxDynamicSharedMemorySize, GSMEM1);
    cudaFuncSetAttribute(mma_gemm_h2f,
                         cudaFuncAttributeMaxDynamicSharedMemorySize, GSMEM2);
    cudaFuncSetAttribute(attn_mma,
                         cudaFuncAttributeMaxDynamicSharedMemorySize, ATTN_SMEM);

    const int n4 = (B_*S_*DM_) / 4;

    // convert Q/K/V inputs to fp16 (batched)
    cvt_act_h3<<<dim3(n4/256, 3), 256>>>((const float4*)Q, (const float4*)K,
                                         (const float4*)V, n4);
    // transpose all 4 weights to fp16 [n][k] (batched)
    split_wT_h4<<<dim3(32, 32, 4), dim3(32, 8)>>>(Wq, Wk, Wv, Wo);
    // Q/K/V projections in one launch (M=256 tiles)
    mma_gemm_h1b<<<dim3(8, 32, 3), 256, GSMEM1>>>(bq, bk, bv);

    // attention -> X fp16 hi/lo into g_Ac0/g_Ac1
    attn_mma<<<dim3(8, 128), 256, ATTN_SMEM>>>(pad);

    // output projection (fp16x2, M=256 tiles, fp32 out)
    mma_gemm_h2f<<<dim3(8, 32), 256, GSMEM2>>>(bo, out);
}

// round 14
// speedup vs baseline: 1.2846x; 1.2846x over previous
#include <cuda_runtime.h>
#include <cuda_bf16.h>
#include <cuda_fp16.h>
#include <mma.h>
#include <math.h>
#include <stdint.h>

using namespace nvcuda;

#define S_   1024
#define DM_  1024
#define B_   8
#define H_   16
#define D_   64

// ---------------- scratch (__device__ globals; no allocation) ----------------
__device__ __half g_Qh[B_*H_*S_*D_];   // projected Q [b,h,s,d] fp16
__device__ __half g_Kh[B_*H_*S_*D_];   // projected K
__device__ __half g_Vh[B_*H_*S_*D_];   // projected V
__device__ __half g_Ac0[B_*S_*DM_];    // converted Q input; then X fp16 hi
__device__ __half g_Ac1[B_*S_*DM_];    // converted K input; then X fp16 residual
__device__ __half g_Ac2[B_*S_*DM_];    // converted V input
__device__ __half g_W3[3*DM_*DM_];     // transposed fp16 weights [n][k] x3 (also Wo)

// ---------------- helpers ----------------
__device__ __forceinline__ uint32_t smem_u32(const void* p) {
    uint32_t a;
    asm("{ .reg .u64 t; cvta.to.shared.u64 t, %1; cvt.u32.u64 %0, t; }"
        : "=r"(a) : "l"(p));
    return a;
}
__device__ __forceinline__ void cp16(uint32_t dst, const void* src) {
    asm volatile("cp.async.cg.shared.global [%0], [%1], 16;" :: "r"(dst), "l"(src));
}
__device__ __forceinline__ uint32_t pack2h(float a, float b) {
    __half ha = __float2half_rn(a), hb = __float2half_rn(b);
    return (uint32_t)__half_as_ushort(ha) |
           ((uint32_t)__half_as_ushort(hb) << 16);
}
__device__ __forceinline__ uint32_t pack2hres(float a, float b, float* ra, float* rb) {
    __half ha = __float2half_rn(a), hb = __float2half_rn(b);
    *ra = a - __half2float(ha);
    *rb = b - __half2float(hb);
    return (uint32_t)__half_as_ushort(ha) |
           ((uint32_t)__half_as_ushort(hb) << 16);
}
__device__ __forceinline__ void ldsm4(uint32_t* r, uint32_t addr) {
    asm volatile("ldmatrix.sync.aligned.m8n8.x4.shared.b16 {%0,%1,%2,%3}, [%4];"
        : "=r"(r[0]), "=r"(r[1]), "=r"(r[2]), "=r"(r[3]) : "r"(addr));
}
__device__ __forceinline__ void ldsm4t(uint32_t* r, uint32_t addr) {
    asm volatile("ldmatrix.sync.aligned.m8n8.x4.trans.shared.b16 {%0,%1,%2,%3}, [%4];"
        : "=r"(r[0]), "=r"(r[1]), "=r"(r[2]), "=r"(r[3]) : "r"(addr));
}
__device__ __forceinline__ void mma16816(float* c,
    uint32_t a0, uint32_t a1, uint32_t a2, uint32_t a3, uint32_t b0, uint32_t b1) {
    asm volatile(
        "mma.sync.aligned.m16n8k16.row.col.f32.f16.f16.f32 "
        "{%0,%1,%2,%3}, {%4,%5,%6,%7}, {%8,%9}, {%0,%1,%2,%3};"
        : "+f"(c[0]), "+f"(c[1]), "+f"(c[2]), "+f"(c[3])
        : "r"(a0), "r"(a1), "r"(a2), "r"(a3), "r"(b0), "r"(b1));
}

// ---------------- conversion kernels (batched over z) ----------------
__global__ __launch_bounds__(256) void cvt_act_h3(
    const float4* __restrict__ Q, const float4* __restrict__ K,
    const float4* __restrict__ V, int n4)
{
    int i = blockIdx.x * 256 + threadIdx.x;
    if (i >= n4) return;
    int z = blockIdx.y;
    const float4* src = (z == 0) ? Q : (z == 1) ? K : V;
    uint2* dst = (uint2*)((z == 0) ? g_Ac0 : (z == 1) ? g_Ac1 : g_Ac2);
    float4 v = src[i];
    uint2 h;
    h.x = pack2h(v.x, v.y);
    h.y = pack2h(v.z, v.w);
    dst[i] = h;
}

// weight transpose fp16, batched: src=W[h][k][d] (n=h*64+d) -> g_W3 + z*DM*DM [n][k]
__global__ __launch_bounds__(256) void split_wT_h3(
    const float* __restrict__ Wq, const float* __restrict__ Wk,
    const float* __restrict__ Wv)
{
    __shared__ float t[32][33];
    int k0 = blockIdx.x * 32, n0 = blockIdx.y * 32;
    int z = blockIdx.z;
    const float* W = (z == 0) ? Wq : (z == 1) ? Wk : Wv;
    __half* out = g_W3 + (size_t)z * DM_ * DM_;
    int tx = threadIdx.x, ty = threadIdx.y;
    #pragma unroll
    for (int i = 0; i < 4; i++) {
        int k = k0 + ty + 8*i, n = n0 + tx;
        t[ty + 8*i][tx] = W[(((size_t)(n >> 6)) * 1024 + k) * 64 + (n & 63)];
    }
    __syncthreads();
    #pragma unroll
    for (int i = 0; i < 4; i++) {
        int n = n0 + ty + 8*i, k = k0 + tx;
        out[(size_t)n * 1024 + k] = __float2half_rn(t[tx][ty + 8*i]);
    }
}

// Wo transpose fp16: src=Wo[k][n] -> g_W3 [n][k]
__global__ __launch_bounds__(256) void split_wT_ho(const float* __restrict__ W)
{
    __shared__ float t[32][33];
    int k0 = blockIdx.x * 32, n0 = blockIdx.y * 32;
    int tx = threadIdx.x, ty = threadIdx.y;
    #pragma unroll
    for (int i = 0; i < 4; i++) {
        int k = k0 + ty + 8*i, n = n0 + tx;
        t[ty + 8*i][tx] = W[(size_t)k * 1024 + n];
    }
    __syncthreads();
    #pragma unroll
    for (int i = 0; i < 4; i++) {
        int n = n0 + ty + 8*i, k = k0 + tx;
        g_W3[(size_t)n * 1024 + k] = __float2half_rn(t[tx][ty + 8*i]);
    }
}

// ---------------- fragment typedefs / sizes (R12 GEMMs, verbatim) ----------
#define LDSM   40
#define MATB   (128 * LDSM * 2)
#define STAGEB1 (2 * MATB)
#define EPLD   132
#define GSMEM1 (128 * EPLD * 4)
#define STAGEB2 (3 * MATB)
#define GSMEM2 (2 * STAGEB2 + 16 * 128 * 4)

typedef wmma::fragment<wmma::matrix_a, 16,16,16, __half, wmma::row_major> HFragA;
typedef wmma::fragment<wmma::matrix_b, 16,16,16, __half, wmma::col_major> HFragB;
typedef wmma::fragment<wmma::accumulator, 16,16,16, float> FragC;

// ---------------- fp16 single-pass GEMM, batched QKV projections ------------
__device__ __forceinline__ void issue_stage_h1(
    const __half* __restrict__ Ah, const __half* __restrict__ Bh,
    uint32_t sbase, int stage, int m0, int n0, int k0, int tid)
{
    #pragma unroll
    for (int u = 0; u < 8; u++) {
        int chunk = u * 128 + tid;
        int mat = chunk >> 9;
        int r   = (chunk >> 2) & 127;
        int c   = chunk & 3;
        const __half* g = (mat == 0)
            ? Ah + (size_t)(m0 + r) * 1024 + k0 + c * 8
            : Bh + (size_t)(n0 + r) * 1024 + k0 + c * 8;
        uint32_t dst = sbase + (uint32_t)(stage * STAGEB1 + mat * MATB + r * (LDSM*2) + c * 16);
        cp16(dst, g);
    }
    asm volatile("cp.async.commit_group;" ::: "memory");
}

__global__ __launch_bounds__(128, 2) void mma_gemm_h1b(
    const float* __restrict__ bq, const float* __restrict__ bk,
    const float* __restrict__ bv)
{
    extern __shared__ char sm[];
    float* sBias = (float*)(sm + 2 * STAGEB1);
    const uint32_t sbase = smem_u32(sm);
    const int tid = threadIdx.x;
    const int wid = tid >> 5;
    const int m0 = blockIdx.y * 128;
    const int n0 = blockIdx.x * 128;
    const int z  = blockIdx.z;
    const int wm = wid >> 1;
    const int wn = wid & 1;

    const __half* Ah = (z == 0) ? g_Ac0 : (z == 1) ? g_Ac1 : g_Ac2;
    const __half* Bh = g_W3 + (size_t)z * DM_ * DM_;
    const float* bias = (z == 0) ? bq : (z == 1) ? bk : bv;
    __half* outH = (z == 0) ? g_Qh : (z == 1) ? g_Kh : g_Vh;

    for (int idx = tid; idx < 16 * 128; idx += 128)
        sBias[idx] = bias[n0 + (idx & 127)];
    __syncthreads();

    FragC acc[4][4];
    #pragma unroll
    for (int i = 0; i < 4; i++)
        #pragma unroll
        for (int j = 0; j < 4; j++)
            wmma::load_matrix_sync(acc[i][j], sBias + wn*64 + j*16, 128, wmma::mem_row_major);

    issue_stage_h1(Ah, Bh, sbase, 0, m0, n0, 0, tid);

    for (int kc = 0; kc < 32; kc++) {
        const int s = kc & 1;
        if (kc + 1 < 32) {
            issue_stage_h1(Ah, Bh, sbase, s ^ 1, m0, n0, (kc + 1) * 32, tid);
            asm volatile("cp.async.wait_group 1;" ::: "memory");
        } else {
            asm volatile("cp.async.wait_group 0;" ::: "memory");
        }
        __syncthreads();

        const __half* stg = (const __half*)(sm + s * STAGEB1);
        const __half* sAh = stg;
        const __half* sBh = stg + 128 * LDSM;

        #pragma unroll
        for (int ks = 0; ks < 2; ks++) {
            HFragA ah[4];
            HFragB bh[4];
            #pragma unroll
            for (int i = 0; i < 4; i++)
                wmma::load_matrix_sync(ah[i], sAh + (wm*64 + i*16) * LDSM + ks*16, LDSM);
            #pragma unroll
            for (int j = 0; j < 4; j++)
                wmma::load_matrix_sync(bh[j], sBh + (wn*64 + j*16) * LDSM + ks*16, LDSM);
            #pragma unroll
            for (int i = 0; i < 4; i++)
                #pragma unroll
                for (int j = 0; j < 4; j++)
                    wmma::mma_sync(acc[i][j], ah[i], bh[j], acc[i][j]);
        }
        __syncthreads();
    }

    float* sEpi = (float*)sm;
    #pragma unroll
    for (int i = 0; i < 4; i++)
        #pragma unroll
        for (int j = 0; j < 4; j++)
            wmma::store_matrix_sync(sEpi + (wm*64 + i*16) * EPLD + wn*64 + j*16,
                                    acc[i][j], EPLD, wmma::mem_row_major);
    __syncthreads();

    #pragma unroll
    for (int u = 0; u < 64; u++) {
        int e2 = u * 128 + tid;
        int r = e2 >> 6;
        int c = (e2 & 63) * 2;
        float v0 = sEpi[r * EPLD + c];
        float v1 = sEpi[r * EPLD + c + 1];
        uint32_t hv = pack2h(v0, v1);
        const int m = m0 + r, n = n0 + c;
        const int b = m >> 10, srow = m & 1023;
        const int h = n >> 6,  d = n & 63;
        size_t addr = ((((size_t)(b*16 + h)) * 1024 + srow) * 64 + d);
        *(uint32_t*)(outH + addr) = hv;
    }
}

// ---------------- fp16x2 GEMM (output projection, fp32 out) -----------------
__device__ __forceinline__ void issue_stage_h2(
    const __half* __restrict__ Ah, const __half* __restrict__ Al,
    const __half* __restrict__ Bh,
    uint32_t sbase, int stage, int m0, int n0, int k0, int tid)
{
    #pragma unroll
    for (int u = 0; u < 12; u++) {
        int chunk = u * 128 + tid;
        int mat = chunk >> 9;
        int r   = (chunk >> 2) & 127;
        int c   = chunk & 3;
        const __half* g;
        if      (mat == 0) g = Ah + (size_t)(m0 + r) * 1024 + k0 + c * 8;
        else if (mat == 1) g = Al + (size_t)(m0 + r) * 1024 + k0 + c * 8;
        else               g = Bh + (size_t)(n0 + r) * 1024 + k0 + c * 8;
        uint32_t dst = sbase + (uint32_t)(stage * STAGEB2 + mat * MATB + r * (LDSM*2) + c * 16);
        cp16(dst, g);
    }
    asm volatile("cp.async.commit_group;" ::: "memory");
}

__global__ __launch_bounds__(128, 2) void mma_gemm_h2f(
    const float* __restrict__ bias, float* __restrict__ outF)
{
    extern __shared__ char sm[];
    float* sBias = (float*)(sm + 2 * STAGEB2);
    const uint32_t sbase = smem_u32(sm);
    const int tid = threadIdx.x;
    const int wid = tid >> 5;
    const int m0 = blockIdx.y * 128;
    const int n0 = blockIdx.x * 128;
    const int wm = wid >> 1;
    const int wn = wid & 1;

    const __half* Ah = g_Ac0;
    const __half* Al = g_Ac1;
    const __half* Bh = g_W3;

    for (int idx = tid; idx < 16 * 128; idx += 128)
        sBias[idx] = bias[n0 + (idx & 127)];
    __syncthreads();

    FragC acc[4][4];
    #pragma unroll
    for (int i = 0; i < 4; i++)
        #pragma unroll
        for (int j = 0; j < 4; j++)
            wmma::load_matrix_sync(acc[i][j], sBias + wn*64 + j*16, 128, wmma::mem_row_major);

    issue_stage_h2(Ah, Al, Bh, sbase, 0, m0, n0, 0, tid);

    for (int kc = 0; kc < 32; kc++) {
        const int s = kc & 1;
        if (kc + 1 < 32) {
            issue_stage_h2(Ah, Al, Bh, sbase, s ^ 1, m0, n0, (kc + 1) * 32, tid);
            asm volatile("cp.async.wait_group 1;" ::: "memory");
        } else {
            asm volatile("cp.async.wait_group 0;" ::: "memory");
        }
        __syncthreads();

        const __half* stg = (const __half*)(sm + s * STAGEB2);
        const __half* sAh = stg;
        const __half* sAl = stg + 128 * LDSM;
        const __half* sBh = stg + 2 * 128 * LDSM;

        #pragma unroll
        for (int ks = 0; ks < 2; ks++) {
            HFragA ah[4], al[4];
            HFragB bh[4];
            #pragma unroll
            for (int i = 0; i < 4; i++) {
                wmma::load_matrix_sync(ah[i], sAh + (wm*64 + i*16) * LDSM + ks*16, LDSM);
                wmma::load_matrix_sync(al[i], sAl + (wm*64 + i*16) * LDSM + ks*16, LDSM);
            }
            #pragma unroll
            for (int j = 0; j < 4; j++)
                wmma::load_matrix_sync(bh[j], sBh + (wn*64 + j*16) * LDSM + ks*16, LDSM);
            #pragma unroll
            for (int i = 0; i < 4; i++)
                #pragma unroll
                for (int j = 0; j < 4; j++) {
                    wmma::mma_sync(acc[i][j], ah[i], bh[j], acc[i][j]);
                    wmma::mma_sync(acc[i][j], al[i], bh[j], acc[i][j]);
                }
        }
        __syncthreads();
    }

    #pragma unroll
    for (int i = 0; i < 4; i++) {
        const int m = m0 + wm*64 + i*16;
        #pragma unroll
        for (int j = 0; j < 4; j++) {
            const int n = n0 + wn*64 + j*16;
            wmma::store_matrix_sync(outF + (size_t)m * 1024 + n, acc[i][j],
                                    1024, wmma::mem_row_major);
        }
    }
}

// ---------------- flash attention v6: register-resident FA2 core ------------
// mma.sync m16n8k16 + ldmatrix; S/P/O never touch smem. 2 q-tiles/CTA.
#define ALD 72
#define SLD 68
#define TQB 9216
#define oQ   0                          // 2 groups x 1 fp16 tile  18432
#define oKV  18432                      // 2 stages x 2 tiles      36864
#define oS   55296                      // 2 groups fp32 64xSLD    34816
#define ATTN_SMEM 90112
#define KVSTG (2 * TQB)

__global__ __launch_bounds__(256, 2) void attn_mma(const int* __restrict__ pad)
{
    extern __shared__ char sm[];
    const uint32_t sbase = smem_u32(sm);
    const int tid  = threadIdx.x;
    const int w    = tid >> 5, lane = tid & 31;
    const int g    = w >> 2,   wr   = w & 3;
    const int bx   = blockIdx.x;
    const int bh   = blockIdx.y;
    const int b    = bh >> 4, h = bh & 15;
    const int padb = pad[b];
    const int tlim = S_ - padb;
    const int qt   = bx * 2 + g;
    const int q0   = qt * 64;
    const size_t hoff = (size_t)bh * S_ * D_;

    float* sSg = (float*)(sm + oS + g * 17408);
    const uint32_t sQbase = sbase + oQ + (uint32_t)g * TQB;

    // preload: Q tiles (both groups) + K/V tile 0 into stage 0
    #pragma unroll
    for (int u = 0; u < 4; u++) {
        int c = u * 256 + tid;
        int gm = c >> 9;
        int rc = c & 511;
        int r = rc >> 3, cc = rc & 7;
        const __half* src = g_Qh + hoff + (size_t)((bx*2 + gm) * 64 + r) * 64 + cc * 8;
        cp16(sbase + oQ + (uint32_t)(gm * TQB + r * 144 + cc * 16), src);
    }
    #pragma unroll
    for (int u = 0; u < 4; u++) {
        int c = u * 256 + tid;
        int mat = c >> 9;
        int rc = c & 511;
        int r = rc >> 3, cc = rc & 7;
        const __half* src = (mat == 0 ? g_Kh : g_Vh) + hoff + (size_t)r * 64 + cc * 8;
        cp16(sbase + oKV + (uint32_t)(mat * TQB + r * 144 + cc * 16), src);
    }
    asm volatile("cp.async.commit_group;" ::: "memory");

    const int jtLast = (padb == 0) ? 15 : min(bx * 2 + 1, (tlim - 1) >> 6);

    // lane/fragment geometry (mma.sync m16n8k16)
    const int qrow = lane >> 2;          // 0..7
    const int qcol = lane & 3;           // 0..3
    const int r0g = q0 + wr * 16 + qrow; // global row of c0/c1
    const int r1g = r0g + 8;             // global row of c2/c3

    // ldmatrix lane-address components
    const int l7   = lane & 7;
    const int lb3  = (lane >> 3) & 1;
    const int lb4  = (lane >> 4) & 1;

    float o[8][4];
    #pragma unroll
    for (int nb = 0; nb < 8; nb++)
        #pragma unroll
        for (int k = 0; k < 4; k++) o[nb][k] = 0.f;
    float mr0 = -INFINITY, mr1 = -INFINITY, lr0 = 0.f, lr1 = 0.f;

    uint32_t qf[4][4];   // Q A-fragments, loaded once at jt==0

    for (int jt = 0; jt <= jtLast; jt++) {
        const int s = jt & 1;
        const int t0 = jt * 64;
        if (jt < jtLast) {
            const int tn = (jt + 1) * 64;
            #pragma unroll
            for (int u = 0; u < 4; u++) {
                int c = u * 256 + tid;
                int mat = c >> 9;
                int rc = c & 511;
                int r = rc >> 3, cc = rc & 7;
                const __half* src = (mat == 0 ? g_Kh : g_Vh) + hoff + (size_t)(tn + r) * 64 + cc * 8;
                cp16(sbase + oKV + (uint32_t)((s ^ 1) * KVSTG + mat * TQB + r * 144 + cc * 16), src);
            }
            asm volatile("cp.async.commit_group;" ::: "memory");
            asm volatile("cp.async.wait_group 1;" ::: "memory");
        } else {
            asm volatile("cp.async.wait_group 0;" ::: "memory");
        }
        __syncthreads();

        if (jt == 0) {
            // A fragment per k-step: rows wr*16 + (l7 + lb3*8), k = ks*16 + lb4*8
            #pragma unroll
            for (int ks = 0; ks < 4; ks++) {
                uint32_t a = sQbase + (uint32_t)((wr*16 + l7 + lb3*8) * 144 + (ks*16 + lb4*8) * 2);
                ldsm4(qf[ks], a);
            }
        }

        const bool act = (padb == 0) || (jt <= qt && t0 < tlim);
        if (act) {
            const uint32_t kb = sbase + oKV + (uint32_t)(s * KVSTG);
            const uint32_t vb = kb + TQB;

            // ---- S = Q K^T : registers s[8][4] ----
            float sc[8][4];
            #pragma unroll
            for (int nb = 0; nb < 8; nb++)
                #pragma unroll
                for (int k = 0; k < 4; k++) sc[nb][k] = 0.f;

            #pragma unroll
            for (int ds = 0; ds < 4; ds++) {
                #pragma unroll
                for (int tp = 0; tp < 4; tp++) {
                    // lanes0-7:(t+l7,dlow) 8-15:(t+l7,dhigh) 16-23:(t+8+l7,dlow) 24-31:(t+8+l7,dhigh)
                    uint32_t a = kb + (uint32_t)((tp*16 + l7 + lb4*8) * 144 + (ds*16 + lb3*8) * 2);
                    uint32_t kf[4];
                    ldsm4(kf, a);
                    mma16816(sc[2*tp],   qf[ds][0], qf[ds][1], qf[ds][2], qf[ds][3], kf[0], kf[1]);
                    mma16816(sc[2*tp+1], qf[ds][0], qf[ds][1], qf[ds][2], qf[ds][3], kf[2], kf[3]);
                }
            }

            // ---- softmax in registers ----
            float m0 = -INFINITY, m1 = -INFINITY;
            #pragma unroll
            for (int nb = 0; nb < 8; nb++) {
                const int tb = t0 + nb*8 + qcol*2;
                float v0 = sc[nb][0] * 0.03125f;
                float v1 = sc[nb][1] * 0.03125f;
                float v2 = sc[nb][2] * 0.03125f;
                float v3 = sc[nb][3] * 0.03125f;
                if ((tb   > r0g) | (tb   >= tlim) | (padb == 0)) v0 -= 1e9f;
                if ((tb+1 > r0g) | (tb+1 >= tlim) | (padb == 0)) v1 -= 1e9f;
                if ((tb   > r1g) | (tb   >= tlim) | (padb == 0)) v2 -= 1e9f;
                if ((tb+1 > r1g) | (tb+1 >= tlim) | (padb == 0)) v3 -= 1e9f;
                sc[nb][0] = v0; sc[nb][1] = v1; sc[nb][2] = v2; sc[nb][3] = v3;
                m0 = fmaxf(m0, fmaxf(v0, v1));
                m1 = fmaxf(m1, fmaxf(v2, v3));
            }
            m0 = fmaxf(m0, __shfl_xor_sync(0xffffffffu, m0, 1));
            m0 = fmaxf(m0, __shfl_xor_sync(0xffffffffu, m0, 2));
            m1 = fmaxf(m1, __shfl_xor_sync(0xffffffffu, m1, 1));
            m1 = fmaxf(m1, __shfl_xor_sync(0xffffffffu, m1, 2));
            const float mn0 = fmaxf(mr0, m0);
            const float mn1 = fmaxf(mr1, m1);
            const float a0 = __expf(mr0 - mn0);
            const float a1 = __expf(mr1 - mn1);

            uint32_t pl[8], ph[8];
            float ls0 = 0.f, ls1 = 0.f;
            #pragma unroll
            for (int nb = 0; nb < 8; nb++) {
                float p0 = __expf(sc[nb][0] - mn0);
                float p1 = __expf(sc[nb][1] - mn0);
                float p2 = __expf(sc[nb][2] - mn1);
                float p3 = __expf(sc[nb][3] - mn1);
                ls0 += p0 + p1;
                ls1 += p2 + p3;
                pl[nb] = pack2h(p0, p1);
                ph[nb] = pack2h(p2, p3);
                o[nb][0] *= a0; o[nb][1] *= a0;
                o[nb][2] *= a1; o[nb][3] *= a1;
            }
            ls0 += __shfl_xor_sync(0xffffffffu, ls0, 1);
            ls0 += __shfl_xor_sync(0xffffffffu, ls0, 2);
            ls1 += __shfl_xor_sync(0xffffffffu, ls1, 1);
            ls1 += __shfl_xor_sync(0xffffffffu, ls1, 2);
            lr0 = lr0 * a0 + ls0;
            lr1 = lr1 * a1 + ls1;
            mr0 = mn0; mr1 = mn1;

            // ---- O += P V : P fragments direct from registers ----
            #pragma unroll
            for (int ks = 0; ks < 4; ks++) {
                const uint32_t pa0 = pl[2*ks],   pa1 = ph[2*ks];
                const uint32_t pa2 = pl[2*ks+1], pa3 = ph[2*ks+1];
                #pragma unroll
                for (int dp = 0; dp < 4; dp++) {
                    // lanes0-7:(t+l7,dlow) 8-15:(t+8+l7,dlow) 16-23:(t+l7,dhigh) 24-31:(t+8+l7,dhigh)
                    uint32_t a = vb + (uint32_t)((ks*16 + l7 + lb3*8) * 144 + (dp*16 + lb4*8) * 2);
                    uint32_t vf[4];
                    ldsm4t(vf, a);
                    mma16816(o[2*dp],   pa0, pa1, pa2, pa3, vf[0], vf[1]);
                    mma16816(o[2*dp+1], pa0, pa1, pa2, pa3, vf[2], vf[3]);
                }
            }
        }
        __syncthreads();
    }

    // epilogue: normalize in registers, bounce via smem for coalesced pack
    {
        const float inv0 = 1.f / lr0;
        const float inv1 = 1.f / lr1;
        float* d0 = sSg + (wr*16 + qrow) * SLD + qcol*2;
        float* d1 = d0 + 8 * SLD;
        #pragma unroll
        for (int nb = 0; nb < 8; nb++) {
            d0[nb*8]     = o[nb][0] * inv0;
            d0[nb*8 + 1] = o[nb][1] * inv0;
            d1[nb*8]     = o[nb][2] * inv1;
            d1[nb*8 + 1] = o[nb][3] * inv1;
        }
    }
    __syncwarp();
    {
        const int lr_ = lane >> 1, half = lane & 1;
        const int srow = q0 + wr * 16 + lr_;
        const float* Or = sSg + (wr*16 + lr_) * SLD + half * 32;
        const size_t base = ((size_t)(b * S_ + srow)) * DM_ + h * 64 + half * 32;
        #pragma unroll
        for (int c = 0; c < 32; c += 2) {
            float v0 = Or[c], v1 = Or[c+1];
            float r0, r1;
            uint32_t hv = pack2hres(v0, v1, &r0, &r1);
            uint32_t lv = pack2h(r0, r1);
            *(uint32_t*)(g_Ac0 + base + c) = hv;
            *(uint32_t*)(g_Ac1 + base + c) = lv;
        }
    }
}

// ---------------------------------------------------------------------------
extern "C" void kernel_launch(void* const* d_in, const int* in_sizes, int n_in,
                              void* d_out, int out_size)
{
    const float* Q   = (const float*)d_in[0];
    const float* K   = (const float*)d_in[1];
    const float* V   = (const float*)d_in[2];
    const int*   pad = (const int*)  d_in[3];
    const float* Wq  = (const float*)d_in[4];
    const float* bq  = (const float*)d_in[5];
    const float* Wk  = (const float*)d_in[6];
    const float* bk  = (const float*)d_in[7];
    const float* Wv  = (const float*)d_in[8];
    const float* bv  = (const float*)d_in[9];
    const float* Wo  = (const float*)d_in[10];
    const float* bo  = (const float*)d_in[11];
    float* out = (float*)d_out;

    cudaFuncSetAttribute(mma_gemm_h1b,
                         cudaFuncAttributeMaxDynamicSharedMemorySize, GSMEM1);
    cudaFuncSetAttribute(mma_gemm_h2f,
                         cudaFuncAttributeMaxDynamicSharedMemorySize, GSMEM2);
    cudaFuncSetAttribute(attn_mma,
                         cudaFuncAttributeMaxDynamicSharedMemorySize, ATTN_SMEM);

    const int n4 = (B_*S_*DM_) / 4;

    cvt_act_h3<<<dim3(n4/256, 3), 256>>>((const float4*)Q, (const float4*)K,
                                         (const float4*)V, n4);
    split_wT_h3<<<dim3(32, 32, 3), dim3(32, 8)>>>(Wq, Wk, Wv);
    mma_gemm_h1b<<<dim3(8, 64, 3), 128, GSMEM1>>>(bq, bk, bv);

    attn_mma<<<dim3(8, 128), 256, ATTN_SMEM>>>(pad);

    split_wT_ho<<<dim3(32, 32), dim3(32, 8)>>>(Wo);
    mma_gemm_h2f<<<dim3(8, 64), 128, GSMEM2>>>(bo, out);
}

// round 15
// speedup vs baseline: 1.5171x; 1.1810x over previous
#include <cuda_runtime.h>
#include <cuda_bf16.h>
#include <cuda_fp16.h>
#include <mma.h>
#include <math.h>
#include <stdint.h>

using namespace nvcuda;

#define S_   1024
#define DM_  1024
#define B_   8
#define H_   16
#define D_   64

// ---------------- scratch (__device__ globals; no allocation) ----------------
__device__ __half g_Qh[B_*H_*S_*D_];   // projected Q [b,h,s,d] fp16
__device__ __half g_Kh[B_*H_*S_*D_];   // projected K
__device__ __half g_Vh[B_*H_*S_*D_];   // projected V
__device__ __half g_Ac0[B_*S_*DM_];    // converted Q input; then X fp16
__device__ __half g_Ac1[B_*S_*DM_];    // converted K input
__device__ __half g_Ac2[B_*S_*DM_];    // converted V input
__device__ __half g_W4[4*DM_*DM_];     // transposed fp16 weights [n][k]: Wq,Wk,Wv,Wo

// ---------------- helpers ----------------
__device__ __forceinline__ uint32_t smem_u32(const void* p) {
    uint32_t a;
    asm("{ .reg .u64 t; cvta.to.shared.u64 t, %1; cvt.u32.u64 %0, t; }"
        : "=r"(a) : "l"(p));
    return a;
}
__device__ __forceinline__ void cp16(uint32_t dst, const void* src) {
    asm volatile("cp.async.cg.shared.global [%0], [%1], 16;" :: "r"(dst), "l"(src));
}
__device__ __forceinline__ uint32_t pack2h(float a, float b) {
    __half ha = __float2half_rn(a), hb = __float2half_rn(b);
    return (uint32_t)__half_as_ushort(ha) |
           ((uint32_t)__half_as_ushort(hb) << 16);
}
__device__ __forceinline__ void ldsm4(uint32_t* r, uint32_t addr) {
    asm volatile("ldmatrix.sync.aligned.m8n8.x4.shared.b16 {%0,%1,%2,%3}, [%4];"
        : "=r"(r[0]), "=r"(r[1]), "=r"(r[2]), "=r"(r[3]) : "r"(addr));
}
__device__ __forceinline__ void ldsm4t(uint32_t* r, uint32_t addr) {
    asm volatile("ldmatrix.sync.aligned.m8n8.x4.trans.shared.b16 {%0,%1,%2,%3}, [%4];"
        : "=r"(r[0]), "=r"(r[1]), "=r"(r[2]), "=r"(r[3]) : "r"(addr));
}
__device__ __forceinline__ void mma16816(float* c,
    uint32_t a0, uint32_t a1, uint32_t a2, uint32_t a3, uint32_t b0, uint32_t b1) {
    asm volatile(
        "mma.sync.aligned.m16n8k16.row.col.f32.f16.f16.f32 "
        "{%0,%1,%2,%3}, {%4,%5,%6,%7}, {%8,%9}, {%0,%1,%2,%3};"
        : "+f"(c[0]), "+f"(c[1]), "+f"(c[2]), "+f"(c[3])
        : "r"(a0), "r"(a1), "r"(a2), "r"(a3), "r"(b0), "r"(b1));
}

// ---------------- conversion kernels (batched over z) ----------------
__global__ __launch_bounds__(256) void cvt_act_h3(
    const float4* __restrict__ Q, const float4* __restrict__ K,
    const float4* __restrict__ V, int n4)
{
    int i = blockIdx.x * 256 + threadIdx.x;
    if (i >= n4) return;
    int z = blockIdx.y;
    const float4* src = (z == 0) ? Q : (z == 1) ? K : V;
    uint2* dst = (uint2*)((z == 0) ? g_Ac0 : (z == 1) ? g_Ac1 : g_Ac2);
    float4 v = src[i];
    uint2 h;
    h.x = pack2h(v.x, v.y);
    h.y = pack2h(v.z, v.w);
    dst[i] = h;
}

// weight transpose fp16, 4-way batch: z<3 src=W[h][k][d] (n=h*64+d); z=3 src=Wo[k][n]
__global__ __launch_bounds__(256) void split_wT_h4(
    const float* __restrict__ Wq, const float* __restrict__ Wk,
    const float* __restrict__ Wv, const float* __restrict__ Wo)
{
    __shared__ float t[32][33];
    int k0 = blockIdx.x * 32, n0 = blockIdx.y * 32;
    int z = blockIdx.z;
    const float* W = (z == 0) ? Wq : (z == 1) ? Wk : (z == 2) ? Wv : Wo;
    __half* out = g_W4 + (size_t)z * DM_ * DM_;
    int tx = threadIdx.x, ty = threadIdx.y;
    #pragma unroll
    for (int i = 0; i < 4; i++) {
        int k = k0 + ty + 8*i, n = n0 + tx;
        float v = (z < 3) ? W[(((size_t)(n >> 6)) * 1024 + k) * 64 + (n & 63)]
                          : W[(size_t)k * 1024 + n];
        t[ty + 8*i][tx] = v;
    }
    __syncthreads();
    #pragma unroll
    for (int i = 0; i < 4; i++) {
        int n = n0 + ty + 8*i, k = k0 + tx;
        out[(size_t)n * 1024 + k] = __float2half_rn(t[tx][ty + 8*i]);
    }
}

// ---------------- fragment typedefs / sizes ----------------
#define LDSM   40
#define MATB   (128 * LDSM * 2)
#define STAGEB1 (2 * MATB)
#define EPLD   132
#define GSMEM1 (128 * EPLD * 4)                  // proj: epilogue roundtrip 67584
#define GSMEMO (2 * STAGEB1 + 16 * 128 * 4)      // out: mainloop only 49152

typedef wmma::fragment<wmma::matrix_a, 16,16,16, __half, wmma::row_major> HFragA;
typedef wmma::fragment<wmma::matrix_b, 16,16,16, __half, wmma::col_major> HFragB;
typedef wmma::fragment<wmma::accumulator, 16,16,16, float> FragC;

// ---------------- fp16 single-pass GEMM stage loader ------------------------
__device__ __forceinline__ void issue_stage_h1(
    const __half* __restrict__ Ah, const __half* __restrict__ Bh,
    uint32_t sbase, int stage, int m0, int n0, int k0, int tid)
{
    #pragma unroll
    for (int u = 0; u < 8; u++) {
        int chunk = u * 128 + tid;
        int mat = chunk >> 9;
        int r   = (chunk >> 2) & 127;
        int c   = chunk & 3;
        const __half* g = (mat == 0)
            ? Ah + (size_t)(m0 + r) * 1024 + k0 + c * 8
            : Bh + (size_t)(n0 + r) * 1024 + k0 + c * 8;
        uint32_t dst = sbase + (uint32_t)(stage * STAGEB1 + mat * MATB + r * (LDSM*2) + c * 16);
        cp16(dst, g);
    }
    asm volatile("cp.async.commit_group;" ::: "memory");
}

// ---------------- fp16 single-pass GEMM, batched QKV projections ------------
__global__ __launch_bounds__(128, 2) void mma_gemm_h1b(
    const float* __restrict__ bq, const float* __restrict__ bk,
    const float* __restrict__ bv)
{
    extern __shared__ char sm[];
    float* sBias = (float*)(sm + 2 * STAGEB1);
    const uint32_t sbase = smem_u32(sm);
    const int tid = threadIdx.x;
    const int wid = tid >> 5;
    const int m0 = blockIdx.y * 128;
    const int n0 = blockIdx.x * 128;
    const int z  = blockIdx.z;
    const int wm = wid >> 1;
    const int wn = wid & 1;

    const __half* Ah = (z == 0) ? g_Ac0 : (z == 1) ? g_Ac1 : g_Ac2;
    const __half* Bh = g_W4 + (size_t)z * DM_ * DM_;
    const float* bias = (z == 0) ? bq : (z == 1) ? bk : bv;
    __half* outH = (z == 0) ? g_Qh : (z == 1) ? g_Kh : g_Vh;

    for (int idx = tid; idx < 16 * 128; idx += 128)
        sBias[idx] = bias[n0 + (idx & 127)];
    __syncthreads();

    FragC acc[4][4];
    #pragma unroll
    for (int i = 0; i < 4; i++)
        #pragma unroll
        for (int j = 0; j < 4; j++)
            wmma::load_matrix_sync(acc[i][j], sBias + wn*64 + j*16, 128, wmma::mem_row_major);

    issue_stage_h1(Ah, Bh, sbase, 0, m0, n0, 0, tid);

    for (int kc = 0; kc < 32; kc++) {
        const int s = kc & 1;
        if (kc + 1 < 32) {
            issue_stage_h1(Ah, Bh, sbase, s ^ 1, m0, n0, (kc + 1) * 32, tid);
            asm volatile("cp.async.wait_group 1;" ::: "memory");
        } else {
            asm volatile("cp.async.wait_group 0;" ::: "memory");
        }
        __syncthreads();

        const __half* stg = (const __half*)(sm + s * STAGEB1);
        const __half* sAh = stg;
        const __half* sBh = stg + 128 * LDSM;

        #pragma unroll
        for (int ks = 0; ks < 2; ks++) {
            HFragA ah[4];
            HFragB bh[4];
            #pragma unroll
            for (int i = 0; i < 4; i++)
                wmma::load_matrix_sync(ah[i], sAh + (wm*64 + i*16) * LDSM + ks*16, LDSM);
            #pragma unroll
            for (int j = 0; j < 4; j++)
                wmma::load_matrix_sync(bh[j], sBh + (wn*64 + j*16) * LDSM + ks*16, LDSM);
            #pragma unroll
            for (int i = 0; i < 4; i++)
                #pragma unroll
                for (int j = 0; j < 4; j++)
                    wmma::mma_sync(acc[i][j], ah[i], bh[j], acc[i][j]);
        }
        __syncthreads();
    }

    float* sEpi = (float*)sm;
    #pragma unroll
    for (int i = 0; i < 4; i++)
        #pragma unroll
        for (int j = 0; j < 4; j++)
            wmma::store_matrix_sync(sEpi + (wm*64 + i*16) * EPLD + wn*64 + j*16,
                                    acc[i][j], EPLD, wmma::mem_row_major);
    __syncthreads();

    #pragma unroll
    for (int u = 0; u < 64; u++) {
        int e2 = u * 128 + tid;
        int r = e2 >> 6;
        int c = (e2 & 63) * 2;
        float v0 = sEpi[r * EPLD + c];
        float v1 = sEpi[r * EPLD + c + 1];
        uint32_t hv = pack2h(v0, v1);
        const int m = m0 + r, n = n0 + c;
        const int b = m >> 10, srow = m & 1023;
        const int h = n >> 6,  d = n & 63;
        size_t addr = ((((size_t)(b*16 + h)) * 1024 + srow) * 64 + d);
        *(uint32_t*)(outH + addr) = hv;
    }
}

// ---------------- fp16 single-pass GEMM (output projection, fp32 out) -------
__global__ __launch_bounds__(128, 2) void mma_gemm_h1f(
    const float* __restrict__ bias, float* __restrict__ outF)
{
    extern __shared__ char sm[];
    float* sBias = (float*)(sm + 2 * STAGEB1);
    const uint32_t sbase = smem_u32(sm);
    const int tid = threadIdx.x;
    const int wid = tid >> 5;
    const int m0 = blockIdx.y * 128;
    const int n0 = blockIdx.x * 128;
    const int wm = wid >> 1;
    const int wn = wid & 1;

    const __half* Ah = g_Ac0;                     // X fp16
    const __half* Bh = g_W4 + (size_t)3 * DM_ * DM_;  // Wo fp16 [n][k]

    for (int idx = tid; idx < 16 * 128; idx += 128)
        sBias[idx] = bias[n0 + (idx & 127)];
    __syncthreads();

    FragC acc[4][4];
    #pragma unroll
    for (int i = 0; i < 4; i++)
        #pragma unroll
        for (int j = 0; j < 4; j++)
            wmma::load_matrix_sync(acc[i][j], sBias + wn*64 + j*16, 128, wmma::mem_row_major);

    issue_stage_h1(Ah, Bh, sbase, 0, m0, n0, 0, tid);

    for (int kc = 0; kc < 32; kc++) {
        const int s = kc & 1;
        if (kc + 1 < 32) {
            issue_stage_h1(Ah, Bh, sbase, s ^ 1, m0, n0, (kc + 1) * 32, tid);
            asm volatile("cp.async.wait_group 1;" ::: "memory");
        } else {
            asm volatile("cp.async.wait_group 0;" ::: "memory");
        }
        __syncthreads();

        const __half* stg = (const __half*)(sm + s * STAGEB1);
        const __half* sAh = stg;
        const __half* sBh = stg + 128 * LDSM;

        #pragma unroll
        for (int ks = 0; ks < 2; ks++) {
            HFragA ah[4];
            HFragB bh[4];
            #pragma unroll
            for (int i = 0; i < 4; i++)
                wmma::load_matrix_sync(ah[i], sAh + (wm*64 + i*16) * LDSM + ks*16, LDSM);
            #pragma unroll
            for (int j = 0; j < 4; j++)
                wmma::load_matrix_sync(bh[j], sBh + (wn*64 + j*16) * LDSM + ks*16, LDSM);
            #pragma unroll
            for (int i = 0; i < 4; i++)
                #pragma unroll
                for (int j = 0; j < 4; j++)
                    wmma::mma_sync(acc[i][j], ah[i], bh[j], acc[i][j]);
        }
        __syncthreads();
    }

    #pragma unroll
    for (int i = 0; i < 4; i++) {
        const int m = m0 + wm*64 + i*16;
        #pragma unroll
        for (int j = 0; j < 4; j++) {
            const int n = n0 + wn*64 + j*16;
            wmma::store_matrix_sync(outF + (size_t)m * 1024 + n, acc[i][j],
                                    1024, wmma::mem_row_major);
        }
    }
}

// ---------------- flash attention v6: register-resident FA2 core ------------
#define ALD 72
#define SLD 68
#define TQB 9216
#define oQ   0
#define oKV  18432
#define oS   55296
#define ATTN_SMEM 90112
#define KVSTG (2 * TQB)

__global__ __launch_bounds__(256, 2) void attn_mma(const int* __restrict__ pad)
{
    extern __shared__ char sm[];
    const uint32_t sbase = smem_u32(sm);
    const int tid  = threadIdx.x;
    const int w    = tid >> 5, lane = tid & 31;
    const int g    = w >> 2,   wr   = w & 3;
    const int bx   = blockIdx.x;
    const int bh   = blockIdx.y;
    const int b    = bh >> 4, h = bh & 15;
    const int padb = pad[b];
    const int tlim = S_ - padb;
    const int qt   = bx * 2 + g;
    const int q0   = qt * 64;
    const size_t hoff = (size_t)bh * S_ * D_;

    float* sSg = (float*)(sm + oS + g * 17408);
    const uint32_t sQbase = sbase + oQ + (uint32_t)g * TQB;

    #pragma unroll
    for (int u = 0; u < 4; u++) {
        int c = u * 256 + tid;
        int gm = c >> 9;
        int rc = c & 511;
        int r = rc >> 3, cc = rc & 7;
        const __half* src = g_Qh + hoff + (size_t)((bx*2 + gm) * 64 + r) * 64 + cc * 8;
        cp16(sbase + oQ + (uint32_t)(gm * TQB + r * 144 + cc * 16), src);
    }
    #pragma unroll
    for (int u = 0; u < 4; u++) {
        int c = u * 256 + tid;
        int mat = c >> 9;
        int rc = c & 511;
        int r = rc >> 3, cc = rc & 7;
        const __half* src = (mat == 0 ? g_Kh : g_Vh) + hoff + (size_t)r * 64 + cc * 8;
        cp16(sbase + oKV + (uint32_t)(mat * TQB + r * 144 + cc * 16), src);
    }
    asm volatile("cp.async.commit_group;" ::: "memory");

    const int jtLast = (padb == 0) ? 15 : min(bx * 2 + 1, (tlim - 1) >> 6);

    const int qrow = lane >> 2;
    const int qcol = lane & 3;
    const int r0g = q0 + wr * 16 + qrow;
    const int r1g = r0g + 8;

    const int l7   = lane & 7;
    const int lb3  = (lane >> 3) & 1;
    const int lb4  = (lane >> 4) & 1;

    float o[8][4];
    #pragma unroll
    for (int nb = 0; nb < 8; nb++)
        #pragma unroll
        for (int k = 0; k < 4; k++) o[nb][k] = 0.f;
    float mr0 = -INFINITY, mr1 = -INFINITY, lr0 = 0.f, lr1 = 0.f;

    uint32_t qf[4][4];

    for (int jt = 0; jt <= jtLast; jt++) {
        const int s = jt & 1;
        const int t0 = jt * 64;
        if (jt < jtLast) {
            const int tn = (jt + 1) * 64;
            #pragma unroll
            for (int u = 0; u < 4; u++) {
                int c = u * 256 + tid;
                int mat = c >> 9;
                int rc = c & 511;
                int r = rc >> 3, cc = rc & 7;
                const __half* src = (mat == 0 ? g_Kh : g_Vh) + hoff + (size_t)(tn + r) * 64 + cc * 8;
                cp16(sbase + oKV + (uint32_t)((s ^ 1) * KVSTG + mat * TQB + r * 144 + cc * 16), src);
            }
            asm volatile("cp.async.commit_group;" ::: "memory");
            asm volatile("cp.async.wait_group 1;" ::: "memory");
        } else {
            asm volatile("cp.async.wait_group 0;" ::: "memory");
        }
        __syncthreads();

        if (jt == 0) {
            #pragma unroll
            for (int ks = 0; ks < 4; ks++) {
                uint32_t a = sQbase + (uint32_t)((wr*16 + l7 + lb3*8) * 144 + (ks*16 + lb4*8) * 2);
                ldsm4(qf[ks], a);
            }
        }

        const bool act = (padb == 0) || (jt <= qt && t0 < tlim);
        if (act) {
            const uint32_t kb = sbase + oKV + (uint32_t)(s * KVSTG);
            const uint32_t vb = kb + TQB;

            float sc[8][4];
            #pragma unroll
            for (int nb = 0; nb < 8; nb++)
                #pragma unroll
                for (int k = 0; k < 4; k++) sc[nb][k] = 0.f;

            #pragma unroll
            for (int ds = 0; ds < 4; ds++) {
                #pragma unroll
                for (int tp = 0; tp < 4; tp++) {
                    uint32_t a = kb + (uint32_t)((tp*16 + l7 + lb4*8) * 144 + (ds*16 + lb3*8) * 2);
                    uint32_t kf[4];
                    ldsm4(kf, a);
                    mma16816(sc[2*tp],   qf[ds][0], qf[ds][1], qf[ds][2], qf[ds][3], kf[0], kf[1]);
                    mma16816(sc[2*tp+1], qf[ds][0], qf[ds][1], qf[ds][2], qf[ds][3], kf[2], kf[3]);
                }
            }

            float m0 = -INFINITY, m1 = -INFINITY;
            #pragma unroll
            for (int nb = 0; nb < 8; nb++) {
                const int tb = t0 + nb*8 + qcol*2;
                float v0 = sc[nb][0] * 0.03125f;
                float v1 = sc[nb][1] * 0.03125f;
                float v2 = sc[nb][2] * 0.03125f;
                float v3 = sc[nb][3] * 0.03125f;
                if ((tb   > r0g) | (tb   >= tlim) | (padb == 0)) v0 -= 1e9f;
                if ((tb+1 > r0g) | (tb+1 >= tlim) | (padb == 0)) v1 -= 1e9f;
                if ((tb   > r1g) | (tb   >= tlim) | (padb == 0)) v2 -= 1e9f;
                if ((tb+1 > r1g) | (tb+1 >= tlim) | (padb == 0)) v3 -= 1e9f;
                sc[nb][0] = v0; sc[nb][1] = v1; sc[nb][2] = v2; sc[nb][3] = v3;
                m0 = fmaxf(m0, fmaxf(v0, v1));
                m1 = fmaxf(m1, fmaxf(v2, v3));
            }
            m0 = fmaxf(m0, __shfl_xor_sync(0xffffffffu, m0, 1));
            m0 = fmaxf(m0, __shfl_xor_sync(0xffffffffu, m0, 2));
            m1 = fmaxf(m1, __shfl_xor_sync(0xffffffffu, m1, 1));
            m1 = fmaxf(m1, __shfl_xor_sync(0xffffffffu, m1, 2));
            const float mn0 = fmaxf(mr0, m0);
            const float mn1 = fmaxf(mr1, m1);
            const float a0 = __expf(mr0 - mn0);
            const float a1 = __expf(mr1 - mn1);

            uint32_t pl[8], ph[8];
            float ls0 = 0.f, ls1 = 0.f;
            #pragma unroll
            for (int nb = 0; nb < 8; nb++) {
                float p0 = __expf(sc[nb][0] - mn0);
                float p1 = __expf(sc[nb][1] - mn0);
                float p2 = __expf(sc[nb][2] - mn1);
                float p3 = __expf(sc[nb][3] - mn1);
                ls0 += p0 + p1;
                ls1 += p2 + p3;
                pl[nb] = pack2h(p0, p1);
                ph[nb] = pack2h(p2, p3);
                o[nb][0] *= a0; o[nb][1] *= a0;
                o[nb][2] *= a1; o[nb][3] *= a1;
            }
            ls0 += __shfl_xor_sync(0xffffffffu, ls0, 1);
            ls0 += __shfl_xor_sync(0xffffffffu, ls0, 2);
            ls1 += __shfl_xor_sync(0xffffffffu, ls1, 1);
            ls1 += __shfl_xor_sync(0xffffffffu, ls1, 2);
            lr0 = lr0 * a0 + ls0;
            lr1 = lr1 * a1 + ls1;
            mr0 = mn0; mr1 = mn1;

            #pragma unroll
            for (int ks = 0; ks < 4; ks++) {
                const uint32_t pa0 = pl[2*ks],   pa1 = ph[2*ks];
                const uint32_t pa2 = pl[2*ks+1], pa3 = ph[2*ks+1];
                #pragma unroll
                for (int dp = 0; dp < 4; dp++) {
                    uint32_t a = vb + (uint32_t)((ks*16 + l7 + lb3*8) * 144 + (dp*16 + lb4*8) * 2);
                    uint32_t vf[4];
                    ldsm4t(vf, a);
                    mma16816(o[2*dp],   pa0, pa1, pa2, pa3, vf[0], vf[1]);
                    mma16816(o[2*dp+1], pa0, pa1, pa2, pa3, vf[2], vf[3]);
                }
            }
        }
        __syncthreads();
    }

    // epilogue: normalize in registers, bounce via smem, write X fp16
    {
        const float inv0 = 1.f / lr0;
        const float inv1 = 1.f / lr1;
        float* d0 = sSg + (wr*16 + qrow) * SLD + qcol*2;
        float* d1 = d0 + 8 * SLD;
        #pragma unroll
        for (int nb = 0; nb < 8; nb++) {
            d0[nb*8]     = o[nb][0] * inv0;
            d0[nb*8 + 1] = o[nb][1] * inv0;
            d1[nb*8]     = o[nb][2] * inv1;
            d1[nb*8 + 1] = o[nb][3] * inv1;
        }
    }
    __syncwarp();
    {
        const int lr_ = lane >> 1, half = lane & 1;
        const int srow = q0 + wr * 16 + lr_;
        const float* Or = sSg + (wr*16 + lr_) * SLD + half * 32;
        const size_t base = ((size_t)(b * S_ + srow)) * DM_ + h * 64 + half * 32;
        #pragma unroll
        for (int c = 0; c < 32; c += 2)
            *(uint32_t*)(g_Ac0 + base + c) = pack2h(Or[c], Or[c+1]);
    }
}

// ---------------------------------------------------------------------------
extern "C" void kernel_launch(void* const* d_in, const int* in_sizes, int n_in,
                              void* d_out, int out_size)
{
    const float* Q   = (const float*)d_in[0];
    const float* K   = (const float*)d_in[1];
    const float* V   = (const float*)d_in[2];
    const int*   pad = (const int*)  d_in[3];
    const float* Wq  = (const float*)d_in[4];
    const float* bq  = (const float*)d_in[5];
    const float* Wk  = (const float*)d_in[6];
    const float* bk  = (const float*)d_in[7];
    const float* Wv  = (const float*)d_in[8];
    const float* bv  = (const float*)d_in[9];
    const float* Wo  = (const float*)d_in[10];
    const float* bo  = (const float*)d_in[11];
    float* out = (float*)d_out;

    cudaFuncSetAttribute(mma_gemm_h1b,
                         cudaFuncAttributeMaxDynamicSharedMemorySize, GSMEM1);
    cudaFuncSetAttribute(mma_gemm_h1f,
                         cudaFuncAttributeMaxDynamicSharedMemorySize, GSMEMO);
    cudaFuncSetAttribute(attn_mma,
                         cudaFuncAttributeMaxDynamicSharedMemorySize, ATTN_SMEM);

    const int n4 = (B_*S_*DM_) / 4;

    cvt_act_h3<<<dim3(n4/256, 3), 256>>>((const float4*)Q, (const float4*)K,
                                         (const float4*)V, n4);
    split_wT_h4<<<dim3(32, 32, 4), dim3(32, 8)>>>(Wq, Wk, Wv, Wo);
    mma_gemm_h1b<<<dim3(8, 64, 3), 128, GSMEM1>>>(bq, bk, bv);

    attn_mma<<<dim3(8, 128), 256, ATTN_SMEM>>>(pad);

    mma_gemm_h1f<<<dim3(8, 64), 128, GSMEMO>>>(bo, out);
}